// round 6
// baseline (speedup 1.0000x reference)
#include <cuda_runtime.h>
#include <math.h>

// Problem constants (from reference)
#define Bn    16
#define Tn    512
#define Dn    256
#define Vn    4233
#define LMAXn 64
#define Sn    129          // 2*LMAX+1 extended states
#define NLAB  65           // blank + LMAX distinct label slots per batch
#define BT    (Bn * Tn)    // 8192 rows
#define NCT   34           // ceil(Vn / 128) column tiles
#define NEGF  (-1e30f)
#define LOG2E_F 1.4426950408889634f
#define LN2_F   0.6931471805599453f

typedef unsigned long long ull;

// ---- device scratch (allocation-free rule: static __device__ arrays) ----
__device__ float g_psum[NCT * BT];            // per-coltile partial sum(exp(logit))
__device__ float g_lse[BT];                   // log(sum(exp(logit))) per (b,t)
__device__ float g_lab[Bn * Tn * NLAB];       // raw logits at blank + labels
__device__ float g_ll[Bn];                    // per-batch log-likelihood

__device__ __forceinline__ float ex2f(float x) {
    float r; asm("ex2.approx.ftz.f32 %0, %1;" : "=f"(r) : "f"(x)); return r;
}
__device__ __forceinline__ float lg2f(float x) {
    float r; asm("lg2.approx.ftz.f32 %0, %1;" : "=f"(r) : "f"(x)); return r;
}

// ============================================================
// Kernel A: label logits (raw). Block = (b, 8 t's), 8 warps, one t per warp.
// ============================================================
__global__ __launch_bounds__(256) void ka_label_logits(
    const float* __restrict__ hs, const float* __restrict__ W,
    const float* __restrict__ bias, const int* __restrict__ ys_pad)
{
    __shared__ float hs_s[8][256];
    __shared__ float wsh[256];
    int b   = blockIdx.y;
    int t0  = blockIdx.x * 8;
    int tid = threadIdx.x;
    int w    = tid >> 5;
    int lane = tid & 31;

    const float4* hsg  = (const float4*)(hs + (size_t)(b * Tn + t0) * Dn);
    float4*       hss4 = (float4*)&hs_s[0][0];
    hss4[tid]       = hsg[tid];
    hss4[tid + 256] = hsg[tid + 256];

    float* outrow = g_lab + (size_t)(b * Tn + t0 + w) * NLAB;

    for (int li = 0; li < NLAB; li++) {
        int lab = (li == 0) ? 0 : ys_pad[b * LMAXn + li - 1];
        wsh[tid] = W[(size_t)lab * Dn + tid];
        __syncthreads();
        float partial = 0.f;
        #pragma unroll
        for (int i = 0; i < 8; i++)
            partial += hs_s[w][lane + 32 * i] * wsh[lane + 32 * i];
        #pragma unroll
        for (int d = 16; d >= 1; d >>= 1)
            partial += __shfl_xor_sync(0xffffffffu, partial, d);
        if (lane == 0) {
            outrow[li] = partial + bias[lab];
        }
        __syncthreads();
    }
}

// ============================================================
// Kernel B: tiled SGEMM 128x128xK256 with fused sum(exp) epilogue.
// fp32x2 packed FMA (FFMA2): A duplicated in smem so both operands
// load as natural 64-bit pairs; 32 fma.rn.f32x2 per k per thread.
// ============================================================
__global__ __launch_bounds__(256, 2) void kb_gemm_sumexp(
    const float* __restrict__ hs, const float* __restrict__ W,
    const float* __restrict__ bias)
{
    __shared__ float As2[8][256];   // duplicated pairs: As2[k][2i]=As2[k][2i+1]=A[i][k]
    __shared__ float Bs[8][128];
    int ct = blockIdx.x, rt = blockIdx.y;
    int r0 = rt * 128, c0 = ct * 128;
    int tid = threadIdx.x;

    int lr = tid >> 1;            // 0..127: row (A) / col (B) within tile
    int lk = (tid & 1) * 4;       // 0 or 4: k quad within the 8-wide slab
    const float* Ap = hs + (size_t)(r0 + lr) * Dn + lk;
    int colB = c0 + lr;
    bool colv = colB < Vn;
    const float* Bp = W + (size_t)(colv ? colB : 0) * Dn + lk;

    int tx = tid & 15, ty = tid >> 4;

    ull acc[8][4];                // 8 rows x 4 col-pairs, packed f32x2
    #pragma unroll
    for (int i = 0; i < 8; i++)
        #pragma unroll
        for (int j = 0; j < 4; j++) acc[i][j] = 0ull;

    float4 ra = *(const float4*)Ap;
    float4 rb = colv ? *(const float4*)Bp : make_float4(0.f, 0.f, 0.f, 0.f);

    #pragma unroll 1
    for (int kt = 0; kt < 32; kt++) {
        // store A duplicated as float2 pairs, B plain
        *(float2*)&As2[lk + 0][2 * lr] = make_float2(ra.x, ra.x);
        *(float2*)&As2[lk + 1][2 * lr] = make_float2(ra.y, ra.y);
        *(float2*)&As2[lk + 2][2 * lr] = make_float2(ra.z, ra.z);
        *(float2*)&As2[lk + 3][2 * lr] = make_float2(ra.w, ra.w);
        Bs[lk + 0][lr] = rb.x; Bs[lk + 1][lr] = rb.y;
        Bs[lk + 2][lr] = rb.z; Bs[lk + 3][lr] = rb.w;
        __syncthreads();

        if (kt < 31) {   // register prefetch of next K slab
            ra = *(const float4*)(Ap + (kt + 1) * 8);
            rb = colv ? *(const float4*)(Bp + (kt + 1) * 8)
                      : make_float4(0.f, 0.f, 0.f, 0.f);
        }

        #pragma unroll
        for (int k = 0; k < 8; k++) {
            // A pairs: 4 x LDS.128, each = 2 duplicated pairs
            ulonglong2 a01 = *(const ulonglong2*)&As2[k][16 * ty + 0];
            ulonglong2 a23 = *(const ulonglong2*)&As2[k][16 * ty + 4];
            ulonglong2 a45 = *(const ulonglong2*)&As2[k][16 * ty + 8];
            ulonglong2 a67 = *(const ulonglong2*)&As2[k][16 * ty + 12];
            // B pairs: 2 x LDS.128, each = 2 pairs
            ulonglong2 b01 = *(const ulonglong2*)&Bs[k][tx * 8 + 0];
            ulonglong2 b23 = *(const ulonglong2*)&Bs[k][tx * 8 + 4];
            ull av[8] = {a01.x, a01.y, a23.x, a23.y, a45.x, a45.y, a67.x, a67.y};
            ull bv[4] = {b01.x, b01.y, b23.x, b23.y};
            #pragma unroll
            for (int i = 0; i < 8; i++)
                #pragma unroll
                for (int j = 0; j < 4; j++)
                    asm("fma.rn.f32x2 %0, %1, %2, %0;"
                        : "+l"(acc[i][j]) : "l"(av[i]), "l"(bv[j]));
        }
        __syncthreads();
    }

    // epilogue: add bias, sum exp over this tile's 128 cols, reduce across tx
    #pragma unroll
    for (int i = 0; i < 8; i++) {
        float rs = 0.f;
        #pragma unroll
        for (int j = 0; j < 4; j++) {
            int c = c0 + tx * 8 + 2 * j;
            float lo = __uint_as_float((unsigned)(acc[i][j] & 0xffffffffu));
            float hi = __uint_as_float((unsigned)(acc[i][j] >> 32));
            if (c < Vn)     rs += __expf(lo + bias[c]);
            if (c + 1 < Vn) rs += __expf(hi + bias[c + 1]);
        }
        rs += __shfl_xor_sync(0xffffffffu, rs, 1);
        rs += __shfl_xor_sync(0xffffffffu, rs, 2);
        rs += __shfl_xor_sync(0xffffffffu, rs, 4);
        rs += __shfl_xor_sync(0xffffffffu, rs, 8);
        if (tx == 0) g_psum[ct * BT + r0 + ty * 8 + i] = rs;
    }
}

// ============================================================
// Kernel C: combine partials -> log-sum-exp per row
// ============================================================
__global__ void kc_lse()
{
    int r = blockIdx.x * blockDim.x + threadIdx.x;
    if (r < BT) {
        float s = 0.f;
        #pragma unroll
        for (int ct = 0; ct < NCT; ct++) s += g_psum[ct * BT + r];
        g_lse[r] = logf(s);
    }
}

// ============================================================
// Kernel D: CTC forward DP in LOG2 domain, 1 state per thread.
// Block = one batch, 160 threads (129 active states), smem
// double-buffered alpha exchange, one __syncthreads per frame.
// ============================================================
#define DPT 160
__global__ __launch_bounds__(DPT) void kd_ctc_dp(
    const int* __restrict__ hlens, const int* __restrict__ ys_pad,
    const int* __restrict__ ys_lens)
{
    __shared__ float abuf[2][Sn + 2];   // [buf][s+2]; [0..1] = NEG sentinels
    int b = blockIdx.x;
    int s = threadIdx.x;
    bool act = s < Sn;

    // allow[s] = (s odd, s>=3) && y_k != y_{k-1}, k=(s-1)/2
    bool allow = false;
    if (act && (s & 1) && s >= 2) {
        int k = (s - 1) >> 1;
        allow = (ys_pad[b * LMAXn + k] != ys_pad[b * LMAXn + k - 1]);
    }

    const float* lb   = g_lab + (size_t)b * Tn * NLAB;
    const float* lseb = g_lse + b * Tn;
    int lidx = act ? ((s & 1) ? (s >> 1) + 1 : 0) : 0;
    int hlen = hlens[b];

    if (s == 0) {   // sentinels in both buffers
        abuf[0][0] = NEGF; abuf[0][1] = NEGF;
        abuf[1][0] = NEGF; abuf[1][1] = NEGF;
    }

    // t = 0 init (log2 domain)
    float a = NEGF;
    if (act) {
        float lse0 = lseb[0];
        if (s == 0) a = (lb[0] - lse0) * LOG2E_F;
        if (s == 1) a = (lb[1] - lse0) * LOG2E_F;
        abuf[0][s + 2] = a;
    }

    // prefetch logits for t=1
    float lpn  = act ? lb[NLAB + lidx] : 0.f;
    float lsen = lseb[1];
    __syncthreads();

    int cur = 0;
    for (int t = 1; t < Tn; t++) {
        float lp = (lpn - lsen) * LOG2E_F;
        if (t + 1 < Tn) {       // software prefetch next frame
            lsen = lseb[t + 1];
            if (act) lpn = lb[(size_t)(t + 1) * NLAB + lidx];
        }
        if (act) {
            float am1 = abuf[cur][s + 1];
            float am2 = allow ? abuf[cur][s] : NEGF;
            float m  = fmaxf(fmaxf(a, am1), am2);
            float sm = ex2f(a - m) + ex2f(am1 - m) + ex2f(am2 - m);
            float cand = m + lg2f(sm) + lp;
            if (t < hlen) a = cand;
            abuf[cur ^ 1][s + 2] = a;
        }
        __syncthreads();
        cur ^= 1;
    }

    if (s == 0) {
        int last = 2 * ys_lens[b];
        float vl = abuf[cur][last + 2];
        float vp = abuf[cur][last + 1];
        float m  = fmaxf(vl, vp);
        g_ll[b] = LN2_F * (m + lg2f(ex2f(vl - m) + ex2f(vp - m)));
    }
}

// ============================================================
// Kernel E: loss = -sum(ll)/B
// ============================================================
__global__ void ke_final(float* __restrict__ out)
{
    int lane = threadIdx.x;
    float v = (lane < Bn) ? g_ll[lane] : 0.f;
    #pragma unroll
    for (int d = 16; d >= 1; d >>= 1)
        v += __shfl_xor_sync(0xffffffffu, v, d);
    if (lane == 0) out[0] = -v / (float)Bn;
}

// ============================================================
extern "C" void kernel_launch(void* const* d_in, const int* in_sizes, int n_in,
                              void* d_out, int out_size)
{
    const float* hs      = (const float*)d_in[0];   // [B,T,D] f32
    const int*   hlens   = (const int*)d_in[1];     // [B] i32
    const int*   ys_pad  = (const int*)d_in[2];     // [B,LMAX] i32
    const int*   ys_lens = (const int*)d_in[3];     // [B] i32
    const float* W       = (const float*)d_in[4];   // [V,D] f32
    const float* bias    = (const float*)d_in[5];   // [V] f32
    float*       out     = (float*)d_out;           // scalar f32

    ka_label_logits<<<dim3(Tn / 8, Bn), 256>>>(hs, W, bias, ys_pad);
    kb_gemm_sumexp<<<dim3(NCT, BT / 128), 256>>>(hs, W, bias);
    kc_lse<<<32, 256>>>();
    kd_ctc_dp<<<Bn, DPT>>>(hlens, ys_pad, ys_lens);
    ke_final<<<1, 32>>>(out);
}